// round 3
// baseline (speedup 1.0000x reference)
#include <cuda_runtime.h>
#include <cuda_bf16.h>
#include <cstdint>

// ---------------- problem constants ----------------
#define E_DIM 128
#define L_DIM 256
#define H_DIM 12
#define DH_DIM 64
#define D_DIM 768          // H*DH
#define TD_DIM 2304        // 3*D
#define N_ROWS 32768       // E*L
#define LN_EPS 1e-5f

// ---------------- scratch (__device__ globals; no cudaMalloc allowed) ----------------
__device__ float g_proj[(size_t)N_ROWS * TD_DIM];          // QKV projection     (~302 MB)
__device__ float g_scores[(size_t)H_DIM * L_DIM * L_DIM];  // row scores/maps    (~3 MB)
__device__ float g_lnstats[N_ROWS * 2];                    // per-row mu, rstd   (256 KB)
__device__ float g_rowmask[H_DIM * L_DIM];                 // sum_e mask[h,e,j]

// ---------------- reductions ----------------
__device__ __forceinline__ float warp_sum(float v) {
#pragma unroll
    for (int o = 16; o; o >>= 1) v += __shfl_xor_sync(0xffffffffu, v, o);
    return v;
}
__device__ __forceinline__ float warp_max(float v) {
#pragma unroll
    for (int o = 16; o; o >>= 1) v = fmaxf(v, __shfl_xor_sync(0xffffffffu, v, o));
    return v;
}
__device__ __forceinline__ float block_sum256(float v, float* red) {
    int lane = threadIdx.x & 31, w = threadIdx.x >> 5;
    v = warp_sum(v);
    if (lane == 0) red[w] = v;
    __syncthreads();
    if (threadIdx.x < 8) {
        float r = red[threadIdx.x];
        r += __shfl_xor_sync(0xffu, r, 4);
        r += __shfl_xor_sync(0xffu, r, 2);
        r += __shfl_xor_sync(0xffu, r, 1);
        if (threadIdx.x == 0) red[0] = r;
    }
    __syncthreads();
    float out = red[0];
    __syncthreads();
    return out;
}
__device__ __forceinline__ float block_max256(float v, float* red) {
    int lane = threadIdx.x & 31, w = threadIdx.x >> 5;
    v = warp_max(v);
    if (lane == 0) red[w] = v;
    __syncthreads();
    if (threadIdx.x < 8) {
        float r = red[threadIdx.x];
        r = fmaxf(r, __shfl_xor_sync(0xffu, r, 4));
        r = fmaxf(r, __shfl_xor_sync(0xffu, r, 2));
        r = fmaxf(r, __shfl_xor_sync(0xffu, r, 1));
        if (threadIdx.x == 0) red[0] = r;
    }
    __syncthreads();
    float out = red[0];
    __syncthreads();
    return out;
}

// ---------------- K1/K6: LayerNorm stats only (mu, rstd per row) ----------------
__global__ __launch_bounds__(256) void ln_stats_kernel(const float* __restrict__ x) {
    __shared__ float red[8];
    const size_t base = (size_t)blockIdx.x * D_DIM;
    const int t = threadIdx.x;
    float v0 = x[base + t];
    float v1 = x[base + t + 256];
    float v2 = x[base + t + 512];
    float s1 = block_sum256(v0 + v1 + v2, red);
    float s2 = block_sum256(v0 * v0 + v1 * v1 + v2 * v2, red);
    const float inv_d = 1.0f / (float)D_DIM;
    float mu = s1 * inv_d;
    float var = fmaxf(s2 * inv_d - mu * mu, 0.0f);
    if (t == 0) {
        g_lnstats[blockIdx.x * 2 + 0] = mu;
        g_lnstats[blockIdx.x * 2 + 1] = rsqrtf(var + LN_EPS);
    }
}

// ---------------- K2/K7: fused LN + QKV GEMM ----------------
// C[N,2304] = LN(x)[N,768] * W[2304,768]^T + bias, LN applied on the fly.
__global__ __launch_bounds__(256) void qkv_gemm_kernel(const float* __restrict__ x,
                                                       const float* __restrict__ W,
                                                       const float* __restrict__ bias,
                                                       const float* __restrict__ gamma,
                                                       const float* __restrict__ beta) {
    __shared__ float As[16][128];   // [k][m]
    __shared__ float Bs[16][128];   // [k][n]
    __shared__ float mu_s[128], rs_s[128];
    __shared__ float gam_s[16], bet_s[16];
    const int tid = threadIdx.x;
    const int tx = tid & 15, ty = tid >> 4;
    const int m0 = blockIdx.y * 128;
    const int n0 = blockIdx.x * 128;

    if (tid < 128) {
        mu_s[tid] = g_lnstats[(m0 + tid) * 2 + 0];
        rs_s[tid] = g_lnstats[(m0 + tid) * 2 + 1];
    }
    float acc[8][8];
#pragma unroll
    for (int i = 0; i < 8; i++)
#pragma unroll
        for (int j = 0; j < 8; j++) acc[i][j] = 0.0f;
    __syncthreads();

    for (int k0 = 0; k0 < D_DIM; k0 += 16) {
        if (tid < 16) {
            gam_s[tid] = gamma[k0 + tid];
            bet_s[tid] = beta[k0 + tid];
        }
        __syncthreads();
#pragma unroll
        for (int q = 0; q < 2; q++) {
            int id = q * 256 + tid;            // 512 float4 per tile
            int r = id >> 2;
            int c4 = (id & 3) << 2;
            float4 va = *(const float4*)(x + (size_t)(m0 + r) * D_DIM + k0 + c4);
            float mu = mu_s[r], rs = rs_s[r];
            As[c4 + 0][r] = (va.x - mu) * rs * gam_s[c4 + 0] + bet_s[c4 + 0];
            As[c4 + 1][r] = (va.y - mu) * rs * gam_s[c4 + 1] + bet_s[c4 + 1];
            As[c4 + 2][r] = (va.z - mu) * rs * gam_s[c4 + 2] + bet_s[c4 + 2];
            As[c4 + 3][r] = (va.w - mu) * rs * gam_s[c4 + 3] + bet_s[c4 + 3];
            float4 vb = *(const float4*)(W + (size_t)(n0 + r) * D_DIM + k0 + c4);
            Bs[c4 + 0][r] = vb.x; Bs[c4 + 1][r] = vb.y; Bs[c4 + 2][r] = vb.z; Bs[c4 + 3][r] = vb.w;
        }
        __syncthreads();
#pragma unroll
        for (int k = 0; k < 16; k++) {
            float a[8], b[8];
            *(float4*)&a[0] = *(const float4*)&As[k][ty * 8];
            *(float4*)&a[4] = *(const float4*)&As[k][ty * 8 + 4];
            *(float4*)&b[0] = *(const float4*)&Bs[k][tx * 8];
            *(float4*)&b[4] = *(const float4*)&Bs[k][tx * 8 + 4];
#pragma unroll
            for (int i = 0; i < 8; i++)
#pragma unroll
                for (int j = 0; j < 8; j++) acc[i][j] = fmaf(a[i], b[j], acc[i][j]);
        }
        __syncthreads();
    }
#pragma unroll
    for (int i = 0; i < 8; i++) {
        int row = m0 + ty * 8 + i;
#pragma unroll
        for (int j = 0; j < 8; j += 4) {
            int col = n0 + tx * 8 + j;
            float4 v;
            v.x = acc[i][j + 0] + bias[col + 0];
            v.y = acc[i][j + 1] + bias[col + 1];
            v.z = acc[i][j + 2] + bias[col + 2];
            v.w = acc[i][j + 3] + bias[col + 3];
            *(float4*)(g_proj + (size_t)row * TD_DIM + col) = v;
        }
    }
}

// ---------------- K3a: zero scores + row mask sums ----------------
__global__ __launch_bounds__(256) void scores_zero_kernel(const float* __restrict__ mask) {
    size_t idx = (size_t)blockIdx.x * 1024 + threadIdx.x * 4;
    if (idx < (size_t)H_DIM * L_DIM * L_DIM) {
        float4 z = {0.f, 0.f, 0.f, 0.f};
        *(float4*)(g_scores + idx) = z;
    }
    int t = blockIdx.x * 256 + threadIdx.x;   // [0, H*L)
    if (t < H_DIM * L_DIM) {
        int h = t / L_DIM, j = t % L_DIM;
        float s = 0.0f;
        for (int e = 0; e < E_DIM; e++) s += mask[((size_t)h * E_DIM + e) * L_DIM + j];
        g_rowmask[t] = s;
    }
}

// ---------------- K3b: row scores  scores[h,i,j] += sum_{e,c} q[e,i,h,c] k[e,j,h,c] ----------------
__global__ __launch_bounds__(256) void row_scores_kernel() {
    __shared__ float Qs[64][64];  // [c][i]
    __shared__ float Ks[64][64];  // [c][j]
    const int tid = threadIdx.x;
    const int tx = tid & 15, ty = tid >> 4;
    const int it = (blockIdx.x >> 2) * 64;
    const int jt = (blockIdx.x & 3) * 64;
    const int h = blockIdx.y;
    const int e0 = blockIdx.z * 32;
    float acc[4][4];
#pragma unroll
    for (int i = 0; i < 4; i++)
#pragma unroll
        for (int j = 0; j < 4; j++) acc[i][j] = 0.0f;

    for (int e = e0; e < e0 + 32; e++) {
        const float* qbase = g_proj + (size_t)(e * L_DIM) * TD_DIM + h * DH_DIM;
        const float* kbase = qbase + D_DIM;
#pragma unroll
        for (int q = 0; q < 4; q++) {
            int id = q * 256 + tid;       // 1024 float4 each
            int r = id & 63;              // warp-contiguous rows -> conflict-free STS
            int c4 = ((id >> 6) & 15) << 2;
            float4 va = *(const float4*)(qbase + (size_t)(it + r) * TD_DIM + c4);
            Qs[c4 + 0][r] = va.x; Qs[c4 + 1][r] = va.y; Qs[c4 + 2][r] = va.z; Qs[c4 + 3][r] = va.w;
            float4 vb = *(const float4*)(kbase + (size_t)(jt + r) * TD_DIM + c4);
            Ks[c4 + 0][r] = vb.x; Ks[c4 + 1][r] = vb.y; Ks[c4 + 2][r] = vb.z; Ks[c4 + 3][r] = vb.w;
        }
        __syncthreads();
#pragma unroll
        for (int c = 0; c < 64; c++) {
            float a[4], b[4];
            *(float4*)a = *(const float4*)&Qs[c][ty * 4];
            *(float4*)b = *(const float4*)&Ks[c][tx * 4];
#pragma unroll
            for (int i = 0; i < 4; i++)
#pragma unroll
                for (int j = 0; j < 4; j++) acc[i][j] = fmaf(a[i], b[j], acc[i][j]);
        }
        __syncthreads();
    }
#pragma unroll
    for (int i = 0; i < 4; i++)
#pragma unroll
        for (int j = 0; j < 4; j++)
            atomicAdd(&g_scores[((size_t)h * L_DIM + it + ty * 4 + i) * L_DIM + jt + tx * 4 + j],
                      acc[i][j]);
}

// ---------------- K4: softmax over j (adds row mask on the fly) ----------------
__global__ __launch_bounds__(256) void row_softmax_kernel() {
    __shared__ float red[8];
    int h = blockIdx.x / L_DIM;
    float* row = g_scores + (size_t)blockIdx.x * L_DIM;
    float v = row[threadIdx.x] + g_rowmask[h * L_DIM + threadIdx.x];
    float m = block_max256(v, red);
    float p = __expf(v - m);
    float s = block_sum256(p, red);
    row[threadIdx.x] = p / s;
}

// ---------------- K5: row AV + residual ----------------
__global__ __launch_bounds__(256) void row_av_kernel(const float* __restrict__ x,
                                                     float* __restrict__ out) {
    __shared__ float Ms[64][64];  // [jj][i]
    __shared__ float Vs[64][64];  // [jj][c]
    const int tid = threadIdx.x;
    const int tx = tid & 15, ty = tid >> 4;
    const int it = blockIdx.x * 64;
    const int h = blockIdx.y;
    const int e = blockIdx.z;
    const float* vbase = g_proj + (size_t)(e * L_DIM) * TD_DIM + 2 * D_DIM + h * DH_DIM;
    float acc[4][4];
#pragma unroll
    for (int i = 0; i < 4; i++)
#pragma unroll
        for (int j = 0; j < 4; j++) acc[i][j] = 0.0f;

    for (int j0 = 0; j0 < L_DIM; j0 += 64) {
#pragma unroll
        for (int q = 0; q < 4; q++) {
            int id = q * 256 + tid;
            int rI = id & 63;
            int c4 = ((id >> 6) & 15) << 2;
            float4 vm = *(const float4*)(g_scores + ((size_t)h * L_DIM + it + rI) * L_DIM + j0 + c4);
            Ms[c4 + 0][rI] = vm.x; Ms[c4 + 1][rI] = vm.y; Ms[c4 + 2][rI] = vm.z; Ms[c4 + 3][rI] = vm.w;
            int rJ = id >> 4;
            int c42 = (id & 15) << 2;
            *(float4*)&Vs[rJ][c42] = *(const float4*)(vbase + (size_t)(j0 + rJ) * TD_DIM + c42);
        }
        __syncthreads();
#pragma unroll
        for (int jj = 0; jj < 64; jj++) {
            float a[4], b[4];
            *(float4*)a = *(const float4*)&Ms[jj][ty * 4];
            *(float4*)b = *(const float4*)&Vs[jj][tx * 4];
#pragma unroll
            for (int i = 0; i < 4; i++)
#pragma unroll
                for (int j = 0; j < 4; j++) acc[i][j] = fmaf(a[i], b[j], acc[i][j]);
        }
        __syncthreads();
    }
#pragma unroll
    for (int i = 0; i < 4; i++) {
        int li = it + ty * 4 + i;
        size_t off = ((size_t)(e * L_DIM + li)) * D_DIM + h * DH_DIM + tx * 4;
        float4 xr = *(const float4*)(x + off);
        float4 v;
        v.x = xr.x + acc[i][0];
        v.y = xr.y + acc[i][1];
        v.z = xr.z + acc[i][2];
        v.w = xr.w + acc[i][3];
        *(float4*)(out + off) = v;
    }
}

// ---------------- K8: fused column attention, one block per (h,l) ----------------
// Smem: K[c][j] 64x128, V[j][c] 128x64, S[j][i] 128x128 -> 99328 B. Q read from gmem
// into registers (each thread owns 8 i-rows x full c loop via smem-free streaming).
#define COL_SMEM_FLOATS (64 * 128 + 128 * 64 + 128 * 128 + 256)
__global__ __launch_bounds__(256) void col_attn_kernel(const float* __restrict__ mask,
                                                       float* __restrict__ out) {
    extern __shared__ float sm[];
    float* Ks = sm;                    // [c][j]  64 x 128
    float* Vs = Ks + 64 * 128;         // [j][c]  128 x 64
    float* Ss = Vs + 128 * 64;         // [j][i]  128 x 128
    float* red2 = Ss + 128 * 128;      // 256 floats
    const int tid = threadIdx.x;
    const int tx = tid & 15, ty = tid >> 4;
    const int l = blockIdx.x;
    const int h = blockIdx.y;

    const float* qbase = g_proj + (size_t)l * TD_DIM + h * DH_DIM;   // + i*L*TD
    const float* kbase = qbase + D_DIM;
    const float* vbase = qbase + 2 * D_DIM;

    // load K (transposed, row-contiguous mapping -> conflict-free STS) and V (direct)
#pragma unroll
    for (int q = 0; q < 8; q++) {
        int id = q * 256 + tid;                 // 2048 float4 per tensor
        int r = id & 127;
        int c4 = ((id >> 7) & 15) << 2;
        float4 vb = *(const float4*)(kbase + (size_t)r * L_DIM * TD_DIM + c4);
        Ks[(c4 + 0) * 128 + r] = vb.x; Ks[(c4 + 1) * 128 + r] = vb.y;
        Ks[(c4 + 2) * 128 + r] = vb.z; Ks[(c4 + 3) * 128 + r] = vb.w;
        int rJ = id >> 4;
        int c42 = (id & 15) << 2;
        *(float4*)&Vs[rJ * 64 + c42] = *(const float4*)(vbase + (size_t)rJ * L_DIM * TD_DIM + c42);
    }
    __syncthreads();

    // ---- S = Q K^T : i on tx (i = tx*8+ii), j on ty (j = ty*8+jj) ----
    // Q streamed from gmem: thread (tx,ty) needs q[i, c] for i in tx*8..tx*8+7, all c.
    // Loop over c in chunks of 4 (float4 per i-row), 16 c-chunks total.
    {
        float accS[8][8];   // [jj][ii]
#pragma unroll
        for (int j = 0; j < 8; j++)
#pragma unroll
            for (int i = 0; i < 8; i++) accS[j][i] = 0.0f;
        for (int c0 = 0; c0 < 64; c0 += 4) {
            float a[8][4];
#pragma unroll
            for (int ii = 0; ii < 8; ii++) {
                int i = tx * 8 + ii;
                *(float4*)&a[ii][0] = *(const float4*)(qbase + (size_t)i * L_DIM * TD_DIM + c0);
            }
#pragma unroll
            for (int cc = 0; cc < 4; cc++) {
                int c = c0 + cc;
                float bj[8];
                *(float4*)&bj[0] = *(const float4*)&Ks[c * 128 + ty * 8];
                *(float4*)&bj[4] = *(const float4*)&Ks[c * 128 + ty * 8 + 4];
#pragma unroll
                for (int j = 0; j < 8; j++)
#pragma unroll
                    for (int i = 0; i < 8; i++) accS[j][i] = fmaf(a[i][cc], bj[j], accS[j][i]);
            }
        }
#pragma unroll
        for (int jj = 0; jj < 8; jj++) {
            int j = ty * 8 + jj;
            float mk = mask[((size_t)h * E_DIM + j) * L_DIM + l];
#pragma unroll
            for (int i0 = 0; i0 < 8; i0 += 4) {
                float4 v;
                v.x = accS[jj][i0 + 0] + mk;
                v.y = accS[jj][i0 + 1] + mk;
                v.z = accS[jj][i0 + 2] + mk;
                v.w = accS[jj][i0 + 3] + mk;
                *(float4*)&Ss[j * 128 + tx * 8 + i0] = v;
            }
        }
    }
    __syncthreads();

    // ---- softmax over j for each i: 2 threads per i (split j halves) ----
    {
        const int i = tid & 127;
        const int half = tid >> 7;
        const int j0 = half * 64;
        float m = -3.4e38f;
#pragma unroll 8
        for (int j = 0; j < 64; j++) m = fmaxf(m, Ss[(j0 + j) * 128 + i]);
        red2[tid] = m;
        __syncthreads();
        m = fmaxf(red2[i], red2[i + 128]);
        float s = 0.0f;
#pragma unroll 8
        for (int j = 0; j < 64; j++) {
            float p = __expf(Ss[(j0 + j) * 128 + i] - m);
            Ss[(j0 + j) * 128 + i] = p;
            s += p;
        }
        __syncthreads();   // all reads of red2 max done before overwrite
        red2[tid] = s;
        __syncthreads();
        float inv = 1.0f / (red2[i] + red2[i + 128]);
#pragma unroll 8
        for (int j = 0; j < 64; j++) Ss[(j0 + j) * 128 + i] *= inv;
    }
    __syncthreads();

    // ---- O = P V : i on ty (i = ty*8+ii), c on tx (c = tx*4) ----
    {
        float accO[8][4];
#pragma unroll
        for (int i = 0; i < 8; i++)
#pragma unroll
            for (int c = 0; c < 4; c++) accO[i][c] = 0.0f;
#pragma unroll 4
        for (int jj = 0; jj < 128; jj++) {
            float ai[8], bc[4];
            *(float4*)&ai[0] = *(const float4*)&Ss[jj * 128 + ty * 8];
            *(float4*)&ai[4] = *(const float4*)&Ss[jj * 128 + ty * 8 + 4];
            *(float4*)&bc[0] = *(const float4*)&Vs[jj * 64 + tx * 4];
#pragma unroll
            for (int i = 0; i < 8; i++)
#pragma unroll
                for (int c = 0; c < 4; c++) accO[i][c] = fmaf(ai[i], bc[c], accO[i][c]);
        }
#pragma unroll
        for (int ii = 0; ii < 8; ii++) {
            int i = ty * 8 + ii;
            size_t off = ((size_t)i * L_DIM + l) * D_DIM + h * DH_DIM + tx * 4;
            float4 cur = *(const float4*)(out + off);
            cur.x += accO[ii][0];
            cur.y += accO[ii][1];
            cur.z += accO[ii][2];
            cur.w += accO[ii][3];
            *(float4*)(out + off) = cur;
        }
    }
}

// ---------------- launcher ----------------
extern "C" void kernel_launch(void* const* d_in, const int* in_sizes, int n_in,
                              void* d_out, int out_size) {
    const float* x     = (const float*)d_in[0];
    const float* mask  = (const float*)d_in[1];
    const float* w_row = (const float*)d_in[2];
    const float* b_row = (const float*)d_in[3];
    const float* w_col = (const float*)d_in[4];
    const float* b_col = (const float*)d_in[5];
    const float* g1    = (const float*)d_in[6];
    const float* be1   = (const float*)d_in[7];
    const float* g2    = (const float*)d_in[8];
    const float* be2   = (const float*)d_in[9];
    float* out = (float*)d_out;

    const int col_smem = COL_SMEM_FLOATS * (int)sizeof(float);  // ~100 KB
    cudaFuncSetAttribute(col_attn_kernel, cudaFuncAttributeMaxDynamicSharedMemorySize, col_smem);

    // ---- row attention stage ----
    ln_stats_kernel<<<N_ROWS, 256>>>(x);
    qkv_gemm_kernel<<<dim3(TD_DIM / 128, N_ROWS / 128), 256>>>(x, w_row, b_row, g1, be1);
    scores_zero_kernel<<<(H_DIM * L_DIM * L_DIM) / 1024, 256>>>(mask);
    row_scores_kernel<<<dim3(16, H_DIM, 4), 256>>>();
    row_softmax_kernel<<<H_DIM * L_DIM, 256>>>();
    row_av_kernel<<<dim3(4, H_DIM, E_DIM), 256>>>(x, out);   // out = x + row_out

    // ---- column attention stage ----
    ln_stats_kernel<<<N_ROWS, 256>>>(out);
    qkv_gemm_kernel<<<dim3(TD_DIM / 128, N_ROWS / 128), 256>>>(out, w_col, b_col, g2, be2);
    col_attn_kernel<<<dim3(L_DIM, H_DIM), 256, col_smem>>>(mask, out);  // out += col_out
}

// round 5
// speedup vs baseline: 1.2232x; 1.2232x over previous
#include <cuda_runtime.h>
#include <cuda_bf16.h>
#include <cstdint>

// ---------------- problem constants ----------------
#define E_DIM 128
#define L_DIM 256
#define H_DIM 12
#define DH_DIM 64
#define D_DIM 768          // H*DH
#define TD_DIM 2304        // 3*D
#define N_ROWS 32768       // E*L
#define LN_EPS 1e-5f

// ---------------- scratch (__device__ globals; no cudaMalloc allowed) ----------------
__device__ float g_proj[(size_t)N_ROWS * TD_DIM];          // QKV projection     (~302 MB)
__device__ float g_scores[(size_t)H_DIM * L_DIM * L_DIM];  // row scores/maps    (~3 MB)
__device__ float g_lnstats[N_ROWS * 2];                    // per-row mu, rstd   (256 KB)
__device__ float g_rowmask[H_DIM * L_DIM];                 // sum_e mask[h,e,j]

// ---------------- tf32 helpers ----------------
__device__ __forceinline__ unsigned f2tf32(float x) {
    unsigned u;
    asm("cvt.rna.tf32.f32 %0, %1;" : "=r"(u) : "f"(x));
    return u;
}
__device__ __forceinline__ void mma_tf32(float* d, const unsigned* a, const unsigned* b) {
    asm volatile(
        "mma.sync.aligned.m16n8k8.row.col.f32.tf32.tf32.f32 "
        "{%0,%1,%2,%3}, {%4,%5,%6,%7}, {%8,%9}, {%0,%1,%2,%3};\n"
        : "+f"(d[0]), "+f"(d[1]), "+f"(d[2]), "+f"(d[3])
        : "r"(a[0]), "r"(a[1]), "r"(a[2]), "r"(a[3]), "r"(b[0]), "r"(b[1]));
}

// ---------------- reductions ----------------
__device__ __forceinline__ float warp_sum(float v) {
#pragma unroll
    for (int o = 16; o; o >>= 1) v += __shfl_xor_sync(0xffffffffu, v, o);
    return v;
}
__device__ __forceinline__ float warp_max(float v) {
#pragma unroll
    for (int o = 16; o; o >>= 1) v = fmaxf(v, __shfl_xor_sync(0xffffffffu, v, o));
    return v;
}
__device__ __forceinline__ float block_sum256(float v, float* red) {
    int lane = threadIdx.x & 31, w = threadIdx.x >> 5;
    v = warp_sum(v);
    if (lane == 0) red[w] = v;
    __syncthreads();
    if (threadIdx.x < 8) {
        float r = red[threadIdx.x];
        r += __shfl_xor_sync(0xffu, r, 4);
        r += __shfl_xor_sync(0xffu, r, 2);
        r += __shfl_xor_sync(0xffu, r, 1);
        if (threadIdx.x == 0) red[0] = r;
    }
    __syncthreads();
    float out = red[0];
    __syncthreads();
    return out;
}
__device__ __forceinline__ float block_max256(float v, float* red) {
    int lane = threadIdx.x & 31, w = threadIdx.x >> 5;
    v = warp_max(v);
    if (lane == 0) red[w] = v;
    __syncthreads();
    if (threadIdx.x < 8) {
        float r = red[threadIdx.x];
        r = fmaxf(r, __shfl_xor_sync(0xffu, r, 4));
        r = fmaxf(r, __shfl_xor_sync(0xffu, r, 2));
        r = fmaxf(r, __shfl_xor_sync(0xffu, r, 1));
        if (threadIdx.x == 0) red[0] = r;
    }
    __syncthreads();
    float out = red[0];
    __syncthreads();
    return out;
}

// ---------------- K1/K6: LayerNorm stats only (mu, rstd per row) ----------------
__global__ __launch_bounds__(256) void ln_stats_kernel(const float* __restrict__ x) {
    __shared__ float red[8];
    const size_t base = (size_t)blockIdx.x * D_DIM;
    const int t = threadIdx.x;
    float v0 = x[base + t];
    float v1 = x[base + t + 256];
    float v2 = x[base + t + 512];
    float s1 = block_sum256(v0 + v1 + v2, red);
    float s2 = block_sum256(v0 * v0 + v1 * v1 + v2 * v2, red);
    const float inv_d = 1.0f / (float)D_DIM;
    float mu = s1 * inv_d;
    float var = fmaxf(s2 * inv_d - mu * mu, 0.0f);
    if (t == 0) {
        g_lnstats[blockIdx.x * 2 + 0] = mu;
        g_lnstats[blockIdx.x * 2 + 1] = rsqrtf(var + LN_EPS);
    }
}

// ---------------- K2/K7: fused LN + QKV GEMM (tensor cores, 3xTF32) ----------------
// C[N,2304] = LN(x)[N,768] * W[2304,768]^T + bias
// Block tile 128x128, warp tile 32x64 (8 warps), mma.m16n8k8 tf32 x 3 splits.
__global__ __launch_bounds__(256, 2) void qkv_gemm_tc(const float* __restrict__ x,
                                                      const float* __restrict__ W,
                                                      const float* __restrict__ bias,
                                                      const float* __restrict__ gamma,
                                                      const float* __restrict__ beta) {
    __shared__ float As[16][136];   // [k][m], pad 8 -> conflict-free fragment LDS
    __shared__ float Bs[16][136];   // [k][n]
    __shared__ float mu_s[128], rs_s[128];
    const int tid = threadIdx.x;
    const int wid = tid >> 5, lane = tid & 31;
    const int warp_m = (wid >> 1) * 32;      // 0,32,64,96
    const int warp_n = (wid & 1) * 64;       // 0,64
    const int r = lane >> 2, c = lane & 3;
    const int m0 = blockIdx.y * 128;
    const int n0 = blockIdx.x * 128;

    if (tid < 128) {
        mu_s[tid] = g_lnstats[(m0 + tid) * 2 + 0];
        rs_s[tid] = g_lnstats[(m0 + tid) * 2 + 1];
    }

    float acc[2][8][4];
#pragma unroll
    for (int t = 0; t < 2; t++)
#pragma unroll
        for (int u = 0; u < 8; u++)
#pragma unroll
            for (int v = 0; v < 4; v++) acc[t][u][v] = 0.0f;
    __syncthreads();

    for (int k0 = 0; k0 < D_DIM; k0 += 16) {
        // ---- stage tiles (LN applied to A on the fly) ----
#pragma unroll
        for (int q = 0; q < 2; q++) {
            int id = q * 256 + tid;          // 512 float4 per tile
            int rr = id >> 2;                // m or n row
            int c4 = (id & 3) << 2;          // k offset
            float4 va = *(const float4*)(x + (size_t)(m0 + rr) * D_DIM + k0 + c4);
            float4 gm = *(const float4*)(gamma + k0 + c4);
            float4 bt = *(const float4*)(beta + k0 + c4);
            float mu = mu_s[rr], rs = rs_s[rr];
            As[c4 + 0][rr] = (va.x - mu) * rs * gm.x + bt.x;
            As[c4 + 1][rr] = (va.y - mu) * rs * gm.y + bt.y;
            As[c4 + 2][rr] = (va.z - mu) * rs * gm.z + bt.z;
            As[c4 + 3][rr] = (va.w - mu) * rs * gm.w + bt.w;
            float4 vb = *(const float4*)(W + (size_t)(n0 + rr) * D_DIM + k0 + c4);
            Bs[c4 + 0][rr] = vb.x; Bs[c4 + 1][rr] = vb.y;
            Bs[c4 + 2][rr] = vb.z; Bs[c4 + 3][rr] = vb.w;
        }
        __syncthreads();

        // ---- compute: two k8 halves ----
#pragma unroll
        for (int k8 = 0; k8 < 16; k8 += 8) {
            unsigned Ahi[2][4], Alo[2][4];
#pragma unroll
            for (int t = 0; t < 2; t++) {
                int m = warp_m + t * 16 + r;
                float x0 = As[k8 + c][m];
                float x1 = As[k8 + c][m + 8];
                float x2 = As[k8 + c + 4][m];
                float x3 = As[k8 + c + 4][m + 8];
                Ahi[t][0] = f2tf32(x0); Alo[t][0] = f2tf32(x0 - __uint_as_float(Ahi[t][0]));
                Ahi[t][1] = f2tf32(x1); Alo[t][1] = f2tf32(x1 - __uint_as_float(Ahi[t][1]));
                Ahi[t][2] = f2tf32(x2); Alo[t][2] = f2tf32(x2 - __uint_as_float(Ahi[t][2]));
                Ahi[t][3] = f2tf32(x3); Alo[t][3] = f2tf32(x3 - __uint_as_float(Ahi[t][3]));
            }
#pragma unroll
            for (int u = 0; u < 8; u++) {
                int n = warp_n + u * 8 + r;
                float y0 = Bs[k8 + c][n];
                float y1 = Bs[k8 + 4 + c][n];
                unsigned Bhi[2], Blo[2];
                Bhi[0] = f2tf32(y0); Blo[0] = f2tf32(y0 - __uint_as_float(Bhi[0]));
                Bhi[1] = f2tf32(y1); Blo[1] = f2tf32(y1 - __uint_as_float(Bhi[1]));
#pragma unroll
                for (int t = 0; t < 2; t++) {
                    mma_tf32(acc[t][u], Ahi[t], Bhi);
                    mma_tf32(acc[t][u], Ahi[t], Blo);
                    mma_tf32(acc[t][u], Alo[t], Bhi);
                }
            }
        }
        __syncthreads();
    }

    // ---- epilogue: bias add + store ----
#pragma unroll
    for (int t = 0; t < 2; t++) {
        int row0 = m0 + warp_m + t * 16 + r;
#pragma unroll
        for (int u = 0; u < 8; u++) {
            int col = n0 + warp_n + u * 8 + c * 2;
            float2 bz = *(const float2*)(bias + col);
            float2 v0, v1;
            v0.x = acc[t][u][0] + bz.x; v0.y = acc[t][u][1] + bz.y;
            v1.x = acc[t][u][2] + bz.x; v1.y = acc[t][u][3] + bz.y;
            *(float2*)(g_proj + (size_t)row0 * TD_DIM + col) = v0;
            *(float2*)(g_proj + (size_t)(row0 + 8) * TD_DIM + col) = v1;
        }
    }
}

// ---------------- K3a: zero scores + row mask sums ----------------
__global__ __launch_bounds__(256) void scores_zero_kernel(const float* __restrict__ mask) {
    size_t idx = (size_t)blockIdx.x * 1024 + threadIdx.x * 4;
    if (idx < (size_t)H_DIM * L_DIM * L_DIM) {
        float4 z = {0.f, 0.f, 0.f, 0.f};
        *(float4*)(g_scores + idx) = z;
    }
    int t = blockIdx.x * 256 + threadIdx.x;   // [0, H*L)
    if (t < H_DIM * L_DIM) {
        int h = t / L_DIM, j = t % L_DIM;
        float s = 0.0f;
        for (int e = 0; e < E_DIM; e++) s += mask[((size_t)h * E_DIM + e) * L_DIM + j];
        g_rowmask[t] = s;
    }
}

// ---------------- K3b: row scores  scores[h,i,j] += sum_{e,c} q[e,i,h,c] k[e,j,h,c] ----------------
__global__ __launch_bounds__(256) void row_scores_kernel() {
    __shared__ float Qs[64][64];  // [c][i]
    __shared__ float Ks[64][64];  // [c][j]
    const int tid = threadIdx.x;
    const int tx = tid & 15, ty = tid >> 4;
    const int it = (blockIdx.x >> 2) * 64;
    const int jt = (blockIdx.x & 3) * 64;
    const int h = blockIdx.y;
    const int e0 = blockIdx.z * 32;
    float acc[4][4];
#pragma unroll
    for (int i = 0; i < 4; i++)
#pragma unroll
        for (int j = 0; j < 4; j++) acc[i][j] = 0.0f;

    for (int e = e0; e < e0 + 32; e++) {
        const float* qbase = g_proj + (size_t)(e * L_DIM) * TD_DIM + h * DH_DIM;
        const float* kbase = qbase + D_DIM;
#pragma unroll
        for (int q = 0; q < 4; q++) {
            int id = q * 256 + tid;       // 1024 float4 each
            int r = id & 63;              // warp-contiguous rows -> conflict-free STS
            int c4 = ((id >> 6) & 15) << 2;
            float4 va = *(const float4*)(qbase + (size_t)(it + r) * TD_DIM + c4);
            Qs[c4 + 0][r] = va.x; Qs[c4 + 1][r] = va.y; Qs[c4 + 2][r] = va.z; Qs[c4 + 3][r] = va.w;
            float4 vb = *(const float4*)(kbase + (size_t)(jt + r) * TD_DIM + c4);
            Ks[c4 + 0][r] = vb.x; Ks[c4 + 1][r] = vb.y; Ks[c4 + 2][r] = vb.z; Ks[c4 + 3][r] = vb.w;
        }
        __syncthreads();
#pragma unroll
        for (int c = 0; c < 64; c++) {
            float a[4], b[4];
            *(float4*)a = *(const float4*)&Qs[c][ty * 4];
            *(float4*)b = *(const float4*)&Ks[c][tx * 4];
#pragma unroll
            for (int i = 0; i < 4; i++)
#pragma unroll
                for (int j = 0; j < 4; j++) acc[i][j] = fmaf(a[i], b[j], acc[i][j]);
        }
        __syncthreads();
    }
#pragma unroll
    for (int i = 0; i < 4; i++)
#pragma unroll
        for (int j = 0; j < 4; j++)
            atomicAdd(&g_scores[((size_t)h * L_DIM + it + ty * 4 + i) * L_DIM + jt + tx * 4 + j],
                      acc[i][j]);
}

// ---------------- K4: softmax over j (adds row mask on the fly) ----------------
__global__ __launch_bounds__(256) void row_softmax_kernel() {
    __shared__ float red[8];
    int h = blockIdx.x / L_DIM;
    float* row = g_scores + (size_t)blockIdx.x * L_DIM;
    float v = row[threadIdx.x] + g_rowmask[h * L_DIM + threadIdx.x];
    float m = block_max256(v, red);
    float p = __expf(v - m);
    float s = block_sum256(p, red);
    row[threadIdx.x] = p / s;
}

// ---------------- K5: row AV + residual ----------------
__global__ __launch_bounds__(256) void row_av_kernel(const float* __restrict__ x,
                                                     float* __restrict__ out) {
    __shared__ float Ms[64][64];  // [jj][i]
    __shared__ float Vs[64][64];  // [jj][c]
    const int tid = threadIdx.x;
    const int tx = tid & 15, ty = tid >> 4;
    const int it = blockIdx.x * 64;
    const int h = blockIdx.y;
    const int e = blockIdx.z;
    const float* vbase = g_proj + (size_t)(e * L_DIM) * TD_DIM + 2 * D_DIM + h * DH_DIM;
    float acc[4][4];
#pragma unroll
    for (int i = 0; i < 4; i++)
#pragma unroll
        for (int j = 0; j < 4; j++) acc[i][j] = 0.0f;

    for (int j0 = 0; j0 < L_DIM; j0 += 64) {
#pragma unroll
        for (int q = 0; q < 4; q++) {
            int id = q * 256 + tid;
            int rI = id & 63;
            int c4 = ((id >> 6) & 15) << 2;
            float4 vm = *(const float4*)(g_scores + ((size_t)h * L_DIM + it + rI) * L_DIM + j0 + c4);
            Ms[c4 + 0][rI] = vm.x; Ms[c4 + 1][rI] = vm.y; Ms[c4 + 2][rI] = vm.z; Ms[c4 + 3][rI] = vm.w;
            int rJ = id >> 4;
            int c42 = (id & 15) << 2;
            *(float4*)&Vs[rJ][c42] = *(const float4*)(vbase + (size_t)(j0 + rJ) * TD_DIM + c42);
        }
        __syncthreads();
#pragma unroll
        for (int jj = 0; jj < 64; jj++) {
            float a[4], b[4];
            *(float4*)a = *(const float4*)&Ms[jj][ty * 4];
            *(float4*)b = *(const float4*)&Vs[jj][tx * 4];
#pragma unroll
            for (int i = 0; i < 4; i++)
#pragma unroll
                for (int j = 0; j < 4; j++) acc[i][j] = fmaf(a[i], b[j], acc[i][j]);
        }
        __syncthreads();
    }
#pragma unroll
    for (int i = 0; i < 4; i++) {
        int li = it + ty * 4 + i;
        size_t off = ((size_t)(e * L_DIM + li)) * D_DIM + h * DH_DIM + tx * 4;
        float4 xr = *(const float4*)(x + off);
        float4 v;
        v.x = xr.x + acc[i][0];
        v.y = xr.y + acc[i][1];
        v.z = xr.z + acc[i][2];
        v.w = xr.w + acc[i][3];
        *(float4*)(out + off) = v;
    }
}

// ---------------- K8: fused column attention, one block per (h,l) ----------------
#define COL_SMEM_FLOATS (64 * 128 + 128 * 64 + 128 * 128 + 256)
__global__ __launch_bounds__(256) void col_attn_kernel(const float* __restrict__ mask,
                                                       float* __restrict__ out) {
    extern __shared__ float sm[];
    float* Ks = sm;                    // [c][j]  64 x 128
    float* Vs = Ks + 64 * 128;         // [j][c]  128 x 64
    float* Ss = Vs + 128 * 64;         // [j][i]  128 x 128
    float* red2 = Ss + 128 * 128;      // 256 floats
    const int tid = threadIdx.x;
    const int tx = tid & 15, ty = tid >> 4;
    const int l = blockIdx.x;
    const int h = blockIdx.y;

    const float* qbase = g_proj + (size_t)l * TD_DIM + h * DH_DIM;   // + i*L*TD
    const float* kbase = qbase + D_DIM;
    const float* vbase = qbase + 2 * D_DIM;

#pragma unroll
    for (int q = 0; q < 8; q++) {
        int id = q * 256 + tid;                 // 2048 float4 per tensor
        int r = id & 127;
        int c4 = ((id >> 7) & 15) << 2;
        float4 vb = *(const float4*)(kbase + (size_t)r * L_DIM * TD_DIM + c4);
        Ks[(c4 + 0) * 128 + r] = vb.x; Ks[(c4 + 1) * 128 + r] = vb.y;
        Ks[(c4 + 2) * 128 + r] = vb.z; Ks[(c4 + 3) * 128 + r] = vb.w;
        int rJ = id >> 4;
        int c42 = (id & 15) << 2;
        *(float4*)&Vs[rJ * 64 + c42] = *(const float4*)(vbase + (size_t)rJ * L_DIM * TD_DIM + c42);
    }
    __syncthreads();

    // ---- S = Q K^T : i on tx, j on ty; Q streamed from gmem ----
    {
        float accS[8][8];   // [jj][ii]
#pragma unroll
        for (int j = 0; j < 8; j++)
#pragma unroll
            for (int i = 0; i < 8; i++) accS[j][i] = 0.0f;
        for (int c0 = 0; c0 < 64; c0 += 4) {
            float a[8][4];
#pragma unroll
            for (int ii = 0; ii < 8; ii++) {
                int i = tx * 8 + ii;
                *(float4*)&a[ii][0] = *(const float4*)(qbase + (size_t)i * L_DIM * TD_DIM + c0);
            }
#pragma unroll
            for (int cc = 0; cc < 4; cc++) {
                int c = c0 + cc;
                float bj[8];
                *(float4*)&bj[0] = *(const float4*)&Ks[c * 128 + ty * 8];
                *(float4*)&bj[4] = *(const float4*)&Ks[c * 128 + ty * 8 + 4];
#pragma unroll
                for (int j = 0; j < 8; j++)
#pragma unroll
                    for (int i = 0; i < 8; i++) accS[j][i] = fmaf(a[i][cc], bj[j], accS[j][i]);
            }
        }
#pragma unroll
        for (int jj = 0; jj < 8; jj++) {
            int j = ty * 8 + jj;
            float mk = mask[((size_t)h * E_DIM + j) * L_DIM + l];
#pragma unroll
            for (int i0 = 0; i0 < 8; i0 += 4) {
                float4 v;
                v.x = accS[jj][i0 + 0] + mk;
                v.y = accS[jj][i0 + 1] + mk;
                v.z = accS[jj][i0 + 2] + mk;
                v.w = accS[jj][i0 + 3] + mk;
                *(float4*)&Ss[j * 128 + tx * 8 + i0] = v;
            }
        }
    }
    __syncthreads();

    // ---- softmax over j for each i: 2 threads per i ----
    {
        const int i = tid & 127;
        const int half = tid >> 7;
        const int j0 = half * 64;
        float m = -3.4e38f;
#pragma unroll 8
        for (int j = 0; j < 64; j++) m = fmaxf(m, Ss[(j0 + j) * 128 + i]);
        red2[tid] = m;
        __syncthreads();
        m = fmaxf(red2[i], red2[i + 128]);
        float s = 0.0f;
#pragma unroll 8
        for (int j = 0; j < 64; j++) {
            float p = __expf(Ss[(j0 + j) * 128 + i] - m);
            Ss[(j0 + j) * 128 + i] = p;
            s += p;
        }
        __syncthreads();   // all max-reads of red2 complete before overwrite with sums
        red2[tid] = s;
        __syncthreads();
        float inv = 1.0f / (red2[i] + red2[i + 128]);
#pragma unroll 8
        for (int j = 0; j < 64; j++) Ss[(j0 + j) * 128 + i] *= inv;
    }
    __syncthreads();

    // ---- O = P V ----
    {
        float accO[8][4];
#pragma unroll
        for (int i = 0; i < 8; i++)
#pragma unroll
            for (int c = 0; c < 4; c++) accO[i][c] = 0.0f;
#pragma unroll 4
        for (int jj = 0; jj < 128; jj++) {
            float ai[8], bc[4];
            *(float4*)&ai[0] = *(const float4*)&Ss[jj * 128 + ty * 8];
            *(float4*)&ai[4] = *(const float4*)&Ss[jj * 128 + ty * 8 + 4];
            *(float4*)&bc[0] = *(const float4*)&Vs[jj * 64 + tx * 4];
#pragma unroll
            for (int i = 0; i < 8; i++)
#pragma unroll
                for (int c = 0; c < 4; c++) accO[i][c] = fmaf(ai[i], bc[c], accO[i][c]);
        }
#pragma unroll
        for (int ii = 0; ii < 8; ii++) {
            int i = ty * 8 + ii;
            size_t off = ((size_t)i * L_DIM + l) * D_DIM + h * DH_DIM + tx * 4;
            float4 cur = *(const float4*)(out + off);
            cur.x += accO[ii][0];
            cur.y += accO[ii][1];
            cur.z += accO[ii][2];
            cur.w += accO[ii][3];
            *(float4*)(out + off) = cur;
        }
    }
}

// ---------------- launcher ----------------
extern "C" void kernel_launch(void* const* d_in, const int* in_sizes, int n_in,
                              void* d_out, int out_size) {
    const float* x     = (const float*)d_in[0];
    const float* mask  = (const float*)d_in[1];
    const float* w_row = (const float*)d_in[2];
    const float* b_row = (const float*)d_in[3];
    const float* w_col = (const float*)d_in[4];
    const float* b_col = (const float*)d_in[5];
    const float* g1    = (const float*)d_in[6];
    const float* be1   = (const float*)d_in[7];
    const float* g2    = (const float*)d_in[8];
    const float* be2   = (const float*)d_in[9];
    float* out = (float*)d_out;

    const int col_smem = COL_SMEM_FLOATS * (int)sizeof(float);  // ~100 KB
    cudaFuncSetAttribute(col_attn_kernel, cudaFuncAttributeMaxDynamicSharedMemorySize, col_smem);

    // ---- row attention stage ----
    ln_stats_kernel<<<N_ROWS, 256>>>(x);
    qkv_gemm_tc<<<dim3(TD_DIM / 128, N_ROWS / 128), 256>>>(x, w_row, b_row, g1, be1);
    scores_zero_kernel<<<(H_DIM * L_DIM * L_DIM) / 1024, 256>>>(mask);
    row_scores_kernel<<<dim3(16, H_DIM, 4), 256>>>();
    row_softmax_kernel<<<H_DIM * L_DIM, 256>>>();
    row_av_kernel<<<dim3(4, H_DIM, E_DIM), 256>>>(x, out);   // out = x + row_out

    // ---- column attention stage ----
    ln_stats_kernel<<<N_ROWS, 256>>>(out);
    qkv_gemm_tc<<<dim3(TD_DIM / 128, N_ROWS / 128), 256>>>(out, w_col, b_col, g2, be2);
    col_attn_kernel<<<dim3(L_DIM, H_DIM), 256, col_smem>>>(mask, out);  // out += col_out
}